// round 14
// baseline (speedup 1.0000x reference)
#include <cuda_runtime.h>
#include <cuda_bf16.h>
#include <math_constants.h>
#include <cstdint>

#define SEQ   2048
#define HIDN  2048
#define NH    16
#define HD    128
#define NB    32
#define BLK   64
#define TOPK  8
#define SM_SCALE 0.08838834764831845f
// sm_scale * log2(e): scores kept in log2 domain for exp2
#define SM_SCALE_L2 0.1275208126606169f

// ---------------- GEMM config (mma.sync bf16, bf16x3 split) -------------------
// CTA tile 128x256, BK=32, 8 warps of 64x64, 3-stage cp.async ring, 1 CTA/SM.
#define GBM 128
#define GBN 256
#define GBK 32
#define GEMM_K 2048
#define NIT (GEMM_K / GBK)     // 64
#define GRS 80                 // smem row stride bytes (conflict-free ldmatrix)
#define G_AHI 0
#define G_ALO 10240
#define G_BHI 20480
#define G_BLO 40960
#define G_STAGE 61440
#define G_SMEM (3 * G_STAGE)   // 184320

// ---------------- attention smem layout (bf16 tiles, 272B row stride) ----------
#define TSTR 272                        // 64-row tile: 64*272 = 17408 B
#define TILE_B 17408
#define AQH 0
#define AQL (1 * TILE_B)
#define AKH (2 * TILE_B)
#define AKL (3 * TILE_B)
#define AVH (4 * TILE_B)
#define AVL (5 * TILE_B)
#define ATT_SMEM (6 * TILE_B)           // 104448

// ---------------- scratch (static __device__, allocation-free) ----------------
__device__ __nv_bfloat16 g_xh[SEQ * HIDN];
__device__ __nv_bfloat16 g_xl[SEQ * HIDN];
__device__ __nv_bfloat16 g_wth[3 * HIDN * HIDN];   // (Wq|Wk|Wv)^T rows: [6144][2048]
__device__ __nv_bfloat16 g_wtl[3 * HIDN * HIDN];
__device__ __nv_bfloat16 g_woth[HIDN * HIDN];      // Wo^T [2048][2048]
__device__ __nv_bfloat16 g_wotl[HIDN * HIDN];
__device__ __nv_bfloat16 g_atth[SEQ * HIDN];
__device__ __nv_bfloat16 g_attl[SEQ * HIDN];
__device__ float g_qkv[SEQ * 3 * HIDN];            // [s][q|k|v], row stride 6144
__device__ __nv_bfloat16 g_qkvh[SEQ * 3 * HIDN];   // bf16 hi split of g_qkv
__device__ __nv_bfloat16 g_qkvl[SEQ * 3 * HIDN];   // bf16 lo split
__device__ float g_att[SEQ * HIDN];
__device__ float g_kgt[NH * HD * NB];
__device__ uint32_t g_mask[NH * SEQ];              // selected-block bitmask per (h,s)

// ---------------- PTX helpers (sm_80-baseline only: no tcgen05) ---------------
__device__ __forceinline__ uint32_t smem_u32(const void* p) {
    uint32_t a;
    asm("{ .reg .u64 t; cvta.to.shared.u64 t, %1; cvt.u32.u64 %0, t; }" : "=r"(a) : "l"(p));
    return a;
}
__device__ __forceinline__ void cp16(uint32_t dst, const void* src) {
    asm volatile("cp.async.cg.shared.global [%0], [%1], 16;" :: "r"(dst), "l"(src) : "memory");
}
#define CP_COMMIT() asm volatile("cp.async.commit_group;" ::: "memory")
#define CP_WAIT1()  asm volatile("cp.async.wait_group 1;" ::: "memory")
#define CP_WAIT0()  asm volatile("cp.async.wait_group 0;" ::: "memory")

#define LDSM4(R, a) \
    asm volatile("ldmatrix.sync.aligned.m8n8.x4.shared.b16 {%0,%1,%2,%3}, [%4];" \
                 : "=r"((R)[0]), "=r"((R)[1]), "=r"((R)[2]), "=r"((R)[3]) : "r"(a))
#define LDSM4T(R, a) \
    asm volatile("ldmatrix.sync.aligned.m8n8.x4.trans.shared.b16 {%0,%1,%2,%3}, [%4];" \
                 : "=r"((R)[0]), "=r"((R)[1]), "=r"((R)[2]), "=r"((R)[3]) : "r"(a))

#define MMA16816(D, A, B0, B1) \
    asm volatile("mma.sync.aligned.m16n8k16.row.col.f32.bf16.bf16.f32 " \
                 "{%0,%1,%2,%3}, {%4,%5,%6,%7}, {%8,%9}, {%0,%1,%2,%3};" \
                 : "+f"((D)[0]), "+f"((D)[1]), "+f"((D)[2]), "+f"((D)[3]) \
                 : "r"((A)[0]), "r"((A)[1]), "r"((A)[2]), "r"((A)[3]), "r"(B0), "r"(B1))

__device__ __forceinline__ float ex2(float x) {
    float r; asm("ex2.approx.f32 %0, %1;" : "=f"(r) : "f"(x)); return r;
}
__device__ __forceinline__ uint32_t pack_bf16f(float a, float b) {
    __nv_bfloat162 t = __floats2bfloat162_rn(a, b);   // x(lo)=a, y(hi)=b
    return *(uint32_t*)&t;
}

// ---------------- stage loader: A[128,32] hi/lo + B[256,32] hi/lo -------------
__device__ __forceinline__ void load_stage(uint32_t sb,
    const __nv_bfloat16* __restrict__ Ah, const __nv_bfloat16* __restrict__ Al,
    const __nv_bfloat16* __restrict__ Bh, const __nv_bfloat16* __restrict__ Bl,
    int m0, int n0, int k0, int tid)
{
#pragma unroll
    for (int r = 0; r < 2; ++r) {                 // A: 128 rows x 4 16B-chunks
        int c = tid + 256 * r;
        int row = c >> 2, jc = c & 3;
        uint32_t so = (uint32_t)(row * GRS + jc * 16);
        size_t ga = (size_t)(m0 + row) * GEMM_K + k0 + jc * 8;
        cp16(sb + G_AHI + so, Ah + ga);
        cp16(sb + G_ALO + so, Al + ga);
    }
#pragma unroll
    for (int r = 0; r < 4; ++r) {                 // B: 256 rows x 4 16B-chunks
        int c = tid + 256 * r;
        int row = c >> 2, jc = c & 3;
        uint32_t so = (uint32_t)(row * GRS + jc * 16);
        size_t gb = (size_t)(n0 + row) * GEMM_K + k0 + jc * 8;
        cp16(sb + G_BHI + so, Bh + gb);
        cp16(sb + G_BLO + so, Bl + gb);
    }
}

// ---------------- GEMM: C[M,Ntot] = A @ B^T (bf16x3, fp32 accum) --------------
// 8 warps, warp grid 2(m) x 4(n), warp tile 64x64: 32 independent acc chains
// per warp for ILP; ~190 regs; 1 CTA/SM (by smem), 3-stage prefetch ring.
__global__ __launch_bounds__(256, 1)
void gemm_bf16x3(const __nv_bfloat16* __restrict__ Ah, const __nv_bfloat16* __restrict__ Al,
                 const __nv_bfloat16* __restrict__ Bh, const __nv_bfloat16* __restrict__ Bl,
                 float* __restrict__ C, int Ntot)
{
    extern __shared__ char dynsm[];
    const uint32_t sbase = smem_u32(dynsm);
    const int tid = threadIdx.x;
    const int w = tid >> 5, lane = tid & 31;
    const int wm = w & 1, wn = w >> 1;
    const int m0 = blockIdx.y * GBM, n0 = blockIdx.x * GBN;

    float acc[4][8][4];
#pragma unroll
    for (int i = 0; i < 4; ++i)
#pragma unroll
        for (int j = 0; j < 8; ++j)
#pragma unroll
            for (int q = 0; q < 4; ++q) acc[i][j][q] = 0.0f;

    // prologue: stages 0, 1
    load_stage(sbase,           Ah, Al, Bh, Bl, m0, n0, 0,   tid);
    CP_COMMIT();
    load_stage(sbase + G_STAGE, Ah, Al, Bh, Bl, m0, n0, GBK, tid);
    CP_COMMIT();

    const uint32_t lrow = (lane & 15);
    const uint32_t lcol = (lane >> 4) * 16;

    int cb = 0;                         // compute-buffer index (it % 3)
    for (int it = 0; it < NIT; ++it) {
        CP_WAIT1();                     // load(it) complete; load(it+1) may pend
        __syncthreads();                // buffer (it+2)%3 fully consumed by all

        int pb = cb + 2; if (pb >= 3) pb -= 3;
        if (it + 2 < NIT)
            load_stage(sbase + (uint32_t)pb * G_STAGE,
                       Ah, Al, Bh, Bl, m0, n0, (it + 2) * GBK, tid);
        CP_COMMIT();                    // empty group when no loads: keeps count

        const uint32_t sb = sbase + (uint32_t)cb * G_STAGE;
#pragma unroll
        for (int ks = 0; ks < 2; ++ks) {
            const uint32_t kb = (uint32_t)ks * 32 + lcol;
            uint32_t ah[4][4], al[4][4];
#pragma unroll
            for (int mi = 0; mi < 4; ++mi) {
                uint32_t ra = sb + G_AHI + (uint32_t)((wm * 64 + mi * 16 + lrow) * GRS) + kb;
                LDSM4(ah[mi], ra);
                LDSM4(al[mi], ra + (G_ALO - G_AHI));
            }
#pragma unroll
            for (int ni = 0; ni < 4; ++ni) {
                uint32_t rb = sb + G_BHI + (uint32_t)((wn * 64 + ni * 16 + lrow) * GRS) + kb;
                uint32_t bh4[4], bl4[4];
                LDSM4(bh4, rb);
                LDSM4(bl4, rb + (G_BLO - G_BHI));
#pragma unroll
                for (int mi = 0; mi < 4; ++mi)
#pragma unroll
                    for (int hf = 0; hf < 2; ++hf) {
                        int n8 = ni * 2 + hf;
                        MMA16816(acc[mi][n8], ah[mi], bh4[hf], bh4[hf + 2]);
                        MMA16816(acc[mi][n8], ah[mi], bl4[hf], bl4[hf + 2]);
                        MMA16816(acc[mi][n8], al[mi], bh4[hf], bh4[hf + 2]);
                    }
            }
        }
        cb = cb + 1; if (cb == 3) cb = 0;
    }

    // epilogue: direct float2 stores
    const int crow = (lane >> 2);
    const int ccol = (lane & 3) * 2;
#pragma unroll
    for (int mi = 0; mi < 4; ++mi)
#pragma unroll
        for (int n8 = 0; n8 < 8; ++n8) {
            int r0 = m0 + wm * 64 + mi * 16 + crow;
            int cc = n0 + wn * 64 + n8 * 8 + ccol;
            *(float2*)(C + (size_t)r0 * Ntot + cc)       = make_float2(acc[mi][n8][0], acc[mi][n8][1]);
            *(float2*)(C + (size_t)(r0 + 8) * Ntot + cc) = make_float2(acc[mi][n8][2], acc[mi][n8][3]);
        }
}

// ---------------- fp32 -> bf16 hi/lo split (row-major) ------------------------
__global__ void split_rm(const float* __restrict__ in, __nv_bfloat16* __restrict__ oh,
                         __nv_bfloat16* __restrict__ ol, int n4)
{
    int i = blockIdx.x * blockDim.x + threadIdx.x;
    if (i >= n4) return;
    float4 v = ((const float4*)in)[i];
    __nv_bfloat16 h0 = __float2bfloat16_rn(v.x), h1 = __float2bfloat16_rn(v.y);
    __nv_bfloat16 h2 = __float2bfloat16_rn(v.z), h3 = __float2bfloat16_rn(v.w);
    __nv_bfloat16 l0 = __float2bfloat16_rn(v.x - __bfloat162float(h0));
    __nv_bfloat16 l1 = __float2bfloat16_rn(v.y - __bfloat162float(h1));
    __nv_bfloat16 l2 = __float2bfloat16_rn(v.z - __bfloat162float(h2));
    __nv_bfloat16 l3 = __float2bfloat16_rn(v.w - __bfloat162float(h3));
    ((__nv_bfloat162*)oh)[2 * i + 0] = __halves2bfloat162(h0, h1);
    ((__nv_bfloat162*)oh)[2 * i + 1] = __halves2bfloat162(h2, h3);
    ((__nv_bfloat162*)ol)[2 * i + 0] = __halves2bfloat162(l0, l1);
    ((__nv_bfloat162*)ol)[2 * i + 1] = __halves2bfloat162(l2, l3);
}

// ---------------- fp32 [2048,2048] -> transposed bf16 hi/lo (2 mats via z) ----
__global__ void split_tr2(const float* __restrict__ sA, __nv_bfloat16* __restrict__ hA,
                          __nv_bfloat16* __restrict__ lA,
                          const float* __restrict__ sB, __nv_bfloat16* __restrict__ hB,
                          __nv_bfloat16* __restrict__ lB)
{
    const float* in   = blockIdx.z ? sB : sA;
    __nv_bfloat16* oh = blockIdx.z ? hB : hA;
    __nv_bfloat16* ol = blockIdx.z ? lB : lA;
    __shared__ float t[32][33];
    int x = blockIdx.x * 32 + threadIdx.x;
#pragma unroll
    for (int j = 0; j < 4; ++j) {
        int y = blockIdx.y * 32 + threadIdx.y + j * 8;
        t[threadIdx.y + j * 8][threadIdx.x] = in[(size_t)y * 2048 + x];
    }
    __syncthreads();
    int x2 = blockIdx.y * 32 + threadIdx.x;
#pragma unroll
    for (int j = 0; j < 4; ++j) {
        int y2 = blockIdx.x * 32 + threadIdx.y + j * 8;
        float v = t[threadIdx.x][threadIdx.y + j * 8];
        __nv_bfloat16 h = __float2bfloat16_rn(v);
        __nv_bfloat16 l = __float2bfloat16_rn(v - __bfloat162float(h));
        oh[(size_t)y2 * 2048 + x2] = h;
        ol[(size_t)y2 * 2048 + x2] = l;
    }
}

// ---------------- block-mean gate keys ----------------------------------------
__global__ void kg_kernel() {
    int t = blockIdx.x * blockDim.x + threadIdx.x;
    if (t >= NB * HIDN) return;
    int n = t / HIDN;
    int c = t % HIDN;
    float sum = 0.0f;
    const float* kp = g_qkv + (size_t)(n * BLK) * (3 * HIDN) + HIDN + c;
#pragma unroll 8
    for (int i = 0; i < BLK; i++) sum += kp[(size_t)i * (3 * HIDN)];
    g_kgt[(size_t)c * NB + n] = sum * (1.0f / BLK);
}

// ---------------- gating + top-k -> per-(h,s) block bitmask -------------------
__global__ __launch_bounds__(128)
void gate_kernel() {
    int warp = (blockIdx.x * blockDim.x + threadIdx.x) >> 5;
    int lane = threadIdx.x & 31;
    if (warp >= NH * SEQ) return;
    int h = warp / SEQ;
    int s = warp % SEQ;

    const float* qrow = g_qkv + (size_t)s * (3 * HIDN) + h * HD;
    const float* kgp  = g_kgt + (size_t)h * HD * NB + lane;
    float score = 0.0f;
#pragma unroll 8
    for (int d = 0; d < HD; d++)
        score = fmaf(qrow[d], kgp[(size_t)d * NB], score);

    int qb = s >> 6;
    if (lane == qb)      score =  CUDART_INF_F;
    else if (lane > qb)  score = -CUDART_INF_F;

    float val = score;
    uint32_t mask = 0;
#pragma unroll
    for (int t = 0; t < TOPK; t++) {
        float v = val; int idx = lane;
#pragma unroll
        for (int off = 16; off; off >>= 1) {
            float ov = __shfl_xor_sync(0xffffffffu, v, off);
            int   oi = __shfl_xor_sync(0xffffffffu, idx, off);
            if (ov > v || (ov == v && oi < idx)) { v = ov; idx = oi; }
        }
        if (v != -CUDART_INF_F) mask |= (1u << idx);   // -inf picks fully causal-masked -> skip
        if (lane == idx) val = -CUDART_INF_F;
    }
    if (lane == 0) g_mask[(size_t)h * SEQ + s] = mask;
}

// ---------------- tensor-core block-sparse flash attention --------------------
// CTA = (query block qb, head h). 4 warps x 16 query rows. K/V blocks staged
// once into smem (bf16 hi/lo); S and PV via mma with bf16x3 compensation.
__global__ __launch_bounds__(128)
void attn_mma() {
    extern __shared__ char asmem[];
    __shared__ uint32_t s_qmask[64];
    __shared__ uint32_t s_union;
    const uint32_t F = 0xffffffffu;
    const int qb = blockIdx.x, h = blockIdx.y;
    const int tid = threadIdx.x, w = tid >> 5, lane = tid & 31;
    const uint32_t sb = smem_u32(asmem);
    const char* qh_b = (const char*)g_qkvh;
    const char* ql_b = (const char*)g_qkvl;
    const size_t GROW = 3 * HIDN * 2;               // global row bytes (12288)

    if (tid < 64) s_qmask[tid] = g_mask[(size_t)h * SEQ + qb * 64 + tid];
    __syncthreads();
    if (tid == 0) {
        uint32_t u = 0;
#pragma unroll
        for (int i = 0; i < 64; i++) u |= s_qmask[i];
        s_union = u;
    }

    // stage Q tile (hi/lo): rows qb*64 + j, cols h*128..h*128+127
#pragma unroll
    for (int i = tid; i < 1024; i += 128) {
        int row = i >> 4, c = i & 15;
        uint32_t dst = (uint32_t)(row * TSTR + c * 16);
        size_t src = (size_t)(qb * 64 + row) * GROW + (size_t)(h * HD) * 2 + c * 16;
        cp16(sb + AQH + dst, qh_b + src);
        cp16(sb + AQL + dst, ql_b + src);
    }
    CP_COMMIT(); CP_WAIT0();
    __syncthreads();

    const uint32_t um = s_union;
    const int r1 = lane >> 2;
    const int qloc1 = w * 16 + r1, qloc2 = qloc1 + 8;
    const uint32_t qm1 = s_qmask[qloc1], qm2 = s_qmask[qloc2];
    const uint32_t la = (lane & 15), lc = (lane >> 4) * 16;
    const int col2 = 2 * (lane & 3);

    float m1 = -1e30f, m2 = -1e30f, l1 = 0.0f, l2 = 0.0f;
    float O[16][4];
#pragma unroll
    for (int t = 0; t < 16; ++t)
#pragma unroll
        for (int q = 0; q < 4; ++q) O[t][q] = 0.0f;

    for (int b = 0; b <= qb; ++b) {
        if (!((um >> b) & 1u)) continue;
        __syncthreads();   // previous block's smem fully consumed
        // stage K,V (hi/lo)
#pragma unroll
        for (int i = tid; i < 1024; i += 128) {
            int row = i >> 4, c = i & 15;
            uint32_t dst = (uint32_t)(row * TSTR + c * 16);
            size_t gro = (size_t)(b * 64 + row) * GROW;
            size_t ko = gro + (size_t)(HIDN + h * HD) * 2 + c * 16;
            size_t vo = gro + (size_t)(2 * HIDN + h * HD) * 2 + c * 16;
            cp16(sb + AKH + dst, qh_b + ko);
            cp16(sb + AKL + dst, ql_b + ko);
            cp16(sb + AVH + dst, qh_b + vo);
            cp16(sb + AVL + dst, ql_b + vo);
        }
        CP_COMMIT(); CP_WAIT0();
        __syncthreads();

        // ---- S = Q @ K^T (bf16x3) ----
        float S[8][4];
#pragma unroll
        for (int t = 0; t < 8; ++t)
#pragma unroll
            for (int q = 0; q < 4; ++q) S[t][q] = 0.0f;

#pragma unroll
        for (int ks = 0; ks < 8; ++ks) {
            uint32_t qa = sb + AQH + (uint32_t)((w * 16 + la) * TSTR) + ks * 32 + lc;
            uint32_t qh4[4], ql4[4];
            LDSM4(qh4, qa);
            LDSM4(ql4, qa + (AQL - AQH));
#pragma unroll
            for (int jt = 0; jt < 4; ++jt) {
                uint32_t ka = sb + AKH + (uint32_t)((jt * 16 + la) * TSTR) + ks * 32 + lc;
                uint32_t kh4[4], kl4[4];
                LDSM4(kh4, ka);
                LDSM4(kl4, ka + (AKL - AKH));
                MMA16816(S[2 * jt],     qh4, kh4[0], kh4[2]);
                MMA16816(S[2 * jt],     qh4, kl4[0], kl4[2]);
                MMA16816(S[2 * jt],     ql4, kh4[0], kh4[2]);
                MMA16816(S[2 * jt + 1], qh4, kh4[1], kh4[3]);
                MMA16816(S[2 * jt + 1], qh4, kl4[1], kl4[3]);
                MMA16816(S[2 * jt + 1], ql4, kh4[1], kh4[3]);
            }
        }

        // ---- mask + scale (log2 domain) ----
        const bool self = (b == qb);
        const int lim1 = ((qm1 >> b) & 1u) ? (self ? qloc1 : 63) : -1;
        const int lim2 = ((qm2 >> b) & 1u) ? (self ? qloc2 : 63) : -1;
        float mx1 = -1e30f, mx2 = -1e30f;
#pragma unroll
        for (int t = 0; t < 8; ++t) {
            int j0 = t * 8 + col2, j1 = j0 + 1;
            S[t][0] = (j0 <= lim1) ? S[t][0] * SM_SCALE_L2 : -CUDART_INF_F;
            S[t][1] = (j1 <= lim1) ? S[t][1] * SM_SCALE_L2 : -CUDART_INF_F;
            S[t][2] = (j0 <= lim2) ? S[t][2] * SM_SCALE_L2 : -CUDART_INF_F;
            S[t][3] = (j1 <= lim2) ? S[t][3] * SM_SCALE_L2 : -CUDART_INF_F;
            mx1 = fmaxf(mx1, fmaxf(S[t][0], S[t][1]));
            mx2 = fmaxf(mx2, fmaxf(S[t][2], S[t][3]));
        }
        mx1 = fmaxf(mx1, __shfl_xor_sync(F, mx1, 1));
        mx1 = fmaxf(mx1, __shfl_xor_sync(F, mx1, 2));
        mx2 = fmaxf(mx2, __shfl_xor_sync(F, mx2, 1));
        mx2 = fmaxf(mx2, __shfl_xor_sync(F, mx2, 2));
        float mn1 = fmaxf(m1, mx1), mn2 = fmaxf(m2, mx2);
        float corr1 = ex2(m1 - mn1), corr2 = ex2(m2 - mn2);
        m1 = mn1; m2 = mn2;

        // ---- P = exp2(S - m), convert to bf16 hi/lo ----
        float rs1 = 0.0f, rs2 = 0.0f;
        uint32_t ph2[16], pl2[16];
#pragma unroll
        for (int t = 0; t < 8; ++t) {
            float e0 = ex2(S[t][0] - mn1), e1 = ex2(S[t][1] - mn1);
            float e2 = ex2(S[t][2] - mn2), e3 = ex2(S[t][3] - mn2);
            rs1 += e0 + e1; rs2 += e2 + e3;
            __nv_bfloat16 b0 = __float2bfloat16_rn(e0), b1 = __float2bfloat16_rn(e1);
            __nv_bfloat16 b2 = __float2bfloat16_rn(e2), b3 = __float2bfloat16_rn(e3);
            __nv_bfloat162 p01 = __halves2bfloat162(b0, b1);
            __nv_bfloat162 p23 = __halves2bfloat162(b2, b3);
            ph2[2 * t]     = *(uint32_t*)&p01;
            ph2[2 * t + 1] = *(uint32_t*)&p23;
            pl2[2 * t]     = pack_bf16f(e0 - __bfloat162float(b0), e1 - __bfloat162float(b1));
            pl2[2 * t + 1] = pack_bf16f(e2 - __bfloat162float(b2), e3 - __bfloat162float(b3));
        }
        rs1 += __shfl_xor_sync(F, rs1, 1); rs1 += __shfl_xor_sync(F, rs1, 2);
        rs2 += __shfl_xor_sync(F, rs2, 1); rs2 += __shfl_xor_sync(F, rs2, 2);
        l1 = l1 * corr1 + rs1;
        l2 = l2 * corr2 + rs2;

        // ---- rescale O, then O += P @ V (bf16x3) ----
#pragma unroll
        for (int t = 0; t < 16; ++t) {
            O[t][0] *= corr1; O[t][1] *= corr1;
            O[t][2] *= corr2; O[t][3] *= corr2;
        }
#pragma unroll
        for (int ks = 0; ks < 4; ++ks) {
            uint32_t ph[4] = { ph2[4 * ks], ph2[4 * ks + 1], ph2[4 * ks + 2], ph2[4 * ks + 3] };
            uint32_t pl[4] = { pl2[4 * ks], pl2[4 * ks + 1], pl2[4 * ks + 2], pl2[4 * ks + 3] };
#pragma unroll
            for (int dt = 0; dt < 8; ++dt) {
                uint32_t va = sb + AVH + (uint32_t)((ks * 16 + la) * TSTR) + dt * 32 + lc;
                uint32_t vh4[4], vl4[4];
                LDSM4T(vh4, va);
                LDSM4T(vl4, va + (AVL - AVH));
                MMA16816(O[2 * dt],     ph, vh4[0], vh4[1]);
                MMA16816(O[2 * dt],     ph, vl4[0], vl4[1]);
                MMA16816(O[2 * dt],     pl, vh4[0], vh4[1]);
                MMA16816(O[2 * dt + 1], ph, vh4[2], vh4[3]);
                MMA16816(O[2 * dt + 1], ph, vl4[2], vl4[3]);
                MMA16816(O[2 * dt + 1], pl, vh4[2], vh4[3]);
            }
        }
    }

    // ---- epilogue: O /= l, write g_att ----
    float inv1 = 1.0f / l1, inv2 = 1.0f / l2;   // self diag guarantees l > 0
    const int srow1 = qb * 64 + qloc1, srow2 = srow1 + 8;
#pragma unroll
    for (int t = 0; t < 16; ++t) {
        int d = h * HD + t * 8 + col2;
        *(float2*)(g_att + (size_t)srow1 * HIDN + d) = make_float2(O[t][0] * inv1, O[t][1] * inv1);
        *(float2*)(g_att + (size_t)srow2 * HIDN + d) = make_float2(O[t][2] * inv2, O[t][3] * inv2);
    }
}

// ---------------- launch -----------------------------------------------------
extern "C" void kernel_launch(void* const* d_in, const int* in_sizes, int n_in,
                              void* d_out, int out_size) {
    (void)in_sizes; (void)n_in; (void)out_size;
    const float* x  = (const float*)d_in[0];
    const float* Wq = (const float*)d_in[1];
    const float* Wk = (const float*)d_in[2];
    const float* Wv = (const float*)d_in[3];
    const float* Wo = (const float*)d_in[4];
    float* out = (float*)d_out;

    __nv_bfloat16 *xh, *xl, *wth, *wtl, *woth, *wotl, *atth, *attl, *qkvh, *qkvl;
    float *qkv, *att;
    cudaGetSymbolAddress((void**)&xh,   g_xh);
    cudaGetSymbolAddress((void**)&xl,   g_xl);
    cudaGetSymbolAddress((void**)&wth,  g_wth);
    cudaGetSymbolAddress((void**)&wtl,  g_wtl);
    cudaGetSymbolAddress((void**)&woth, g_woth);
    cudaGetSymbolAddress((void**)&wotl, g_wotl);
    cudaGetSymbolAddress((void**)&atth, g_atth);
    cudaGetSymbolAddress((void**)&attl, g_attl);
    cudaGetSymbolAddress((void**)&qkv,  g_qkv);
    cudaGetSymbolAddress((void**)&att,  g_att);
    cudaGetSymbolAddress((void**)&qkvh, g_qkvh);
    cudaGetSymbolAddress((void**)&qkvl, g_qkvl);

    cudaFuncSetAttribute(gemm_bf16x3, cudaFuncAttributeMaxDynamicSharedMemorySize, G_SMEM);
    cudaFuncSetAttribute(attn_mma,    cudaFuncAttributeMaxDynamicSharedMemorySize, ATT_SMEM);

    const int n4x = SEQ * HIDN / 4;
    // launch order keeps gemm1 at kernel slot 4 = the ncu capture slot
    split_rm<<<(n4x + 255) / 256, 256>>>(x, xh, xl, n4x);
    dim3 tb(32, 8);
    split_tr2<<<dim3(64, 64, 2), tb>>>(Wq, wth, wtl,
                                       Wk, wth + HIDN * HIDN, wtl + HIDN * HIDN);
    split_tr2<<<dim3(64, 64, 2), tb>>>(Wv, wth + 2 * HIDN * HIDN, wtl + 2 * HIDN * HIDN,
                                       Wo, woth, wotl);

    gemm_bf16x3<<<dim3(3 * HIDN / GBN, SEQ / GBM), 256, G_SMEM>>>(xh, xl, wth, wtl, qkv, 3 * HIDN);

    const int n4q = SEQ * 3 * HIDN / 4;
    split_rm<<<(n4q + 255) / 256, 256>>>(qkv, qkvh, qkvl, n4q);
    kg_kernel<<<(NB * HIDN + 255) / 256, 256>>>();
    gate_kernel<<<(NH * SEQ) / 4, 128>>>();
    attn_mma<<<dim3(NB, NH), 128, ATT_SMEM>>>();

    split_rm<<<(n4x + 255) / 256, 256>>>(att, atth, attl, n4x);
    gemm_bf16x3<<<dim3(HIDN / GBN, SEQ / GBM), 256, G_SMEM>>>(atth, attl, woth, wotl, out, HIDN);
}

// round 15
// speedup vs baseline: 1.0266x; 1.0266x over previous
#include <cuda_runtime.h>
#include <cuda_bf16.h>
#include <math_constants.h>
#include <cstdint>

#define SEQ   2048
#define HIDN  2048
#define NH    16
#define HD    128
#define NB    32
#define BLK   64
#define TOPK  8
#define SM_SCALE 0.08838834764831845f
// sm_scale * log2(e): scores kept in log2 domain for exp2
#define SM_SCALE_L2 0.1275208126606169f

// ---------------- GEMM config (mma.sync bf16, bf16x3 split) -------------------
#define BM 128
#define BN 128
#define BK 32
#define GEMM_K 2048
#define NIT (GEMM_K / BK)      // 64
#define STAGES 2               // 2-stage prefetch -> 80KB smem -> 2 CTAs/SM
#define RS 40                  // smem row stride in bf16 elems (80 B, pad for ldmatrix)
#define AHI_OFF 0
#define ALO_OFF (BM * RS * 2)          // 10240
#define BHI_OFF (2 * BM * RS * 2)      // 20480
#define BLO_OFF (3 * BM * RS * 2)      // 30720
#define STAGE_B (4 * BM * RS * 2)      // 40960
#define SMEM_DYN (STAGES * STAGE_B)    // 81920

// ---------------- attention smem layout (bf16 tiles, 272B row stride) ----------
#define TSTR 272                        // 64-row tile: 64*272 = 17408 B
#define TILE_B 17408
#define AQH 0
#define AQL (1 * TILE_B)
#define AKH (2 * TILE_B)
#define AKL (3 * TILE_B)
#define AVH (4 * TILE_B)
#define AVL (5 * TILE_B)
#define ATT_SMEM (6 * TILE_B)           // 104448

// ---------------- scratch (static __device__, allocation-free) ----------------
__device__ __nv_bfloat16 g_xh[SEQ * HIDN];
__device__ __nv_bfloat16 g_xl[SEQ * HIDN];
__device__ __nv_bfloat16 g_wth[3 * HIDN * HIDN];   // (Wq|Wk|Wv)^T rows: [6144][2048]
__device__ __nv_bfloat16 g_wtl[3 * HIDN * HIDN];
__device__ __nv_bfloat16 g_woth[HIDN * HIDN];      // Wo^T [2048][2048]
__device__ __nv_bfloat16 g_wotl[HIDN * HIDN];
__device__ float g_qkv[SEQ * 3 * HIDN];            // [s][q|k|v], row stride 6144
__device__ __nv_bfloat16 g_qkvh[SEQ * 3 * HIDN];   // bf16 hi split of g_qkv
__device__ __nv_bfloat16 g_qkvl[SEQ * 3 * HIDN];   // bf16 lo split
__device__ __nv_bfloat16 g_atth[SEQ * HIDN];       // attention out, bf16 hi
__device__ __nv_bfloat16 g_attl[SEQ * HIDN];       // attention out, bf16 lo
__device__ float g_kgt[NH * HD * NB];
__device__ uint32_t g_mask[NH * SEQ];              // selected-block bitmask per (h,s)

// ---------------- PTX helpers (sm_80-baseline only: no tcgen05) ---------------
__device__ __forceinline__ uint32_t smem_u32(const void* p) {
    uint32_t a;
    asm("{ .reg .u64 t; cvta.to.shared.u64 t, %1; cvt.u32.u64 %0, t; }" : "=r"(a) : "l"(p));
    return a;
}
__device__ __forceinline__ void cp16(uint32_t dst, const void* src) {
    asm volatile("cp.async.cg.shared.global [%0], [%1], 16;" :: "r"(dst), "l"(src) : "memory");
}
#define CP_COMMIT() asm volatile("cp.async.commit_group;" ::: "memory")
#define CP_WAIT0()  asm volatile("cp.async.wait_group 0;" ::: "memory")

#define LDSM4(R, a) \
    asm volatile("ldmatrix.sync.aligned.m8n8.x4.shared.b16 {%0,%1,%2,%3}, [%4];" \
                 : "=r"((R)[0]), "=r"((R)[1]), "=r"((R)[2]), "=r"((R)[3]) : "r"(a))
#define LDSM4T(R, a) \
    asm volatile("ldmatrix.sync.aligned.m8n8.x4.trans.shared.b16 {%0,%1,%2,%3}, [%4];" \
                 : "=r"((R)[0]), "=r"((R)[1]), "=r"((R)[2]), "=r"((R)[3]) : "r"(a))

#define MMA16816(D, A, B0, B1) \
    asm volatile("mma.sync.aligned.m16n8k16.row.col.f32.bf16.bf16.f32 " \
                 "{%0,%1,%2,%3}, {%4,%5,%6,%7}, {%8,%9}, {%0,%1,%2,%3};" \
                 : "+f"((D)[0]), "+f"((D)[1]), "+f"((D)[2]), "+f"((D)[3]) \
                 : "r"((A)[0]), "r"((A)[1]), "r"((A)[2]), "r"((A)[3]), "r"(B0), "r"(B1))

__device__ __forceinline__ float ex2(float x) {
    float r; asm("ex2.approx.f32 %0, %1;" : "=f"(r) : "f"(x)); return r;
}
__device__ __forceinline__ uint32_t pack_bf16f(float a, float b) {
    __nv_bfloat162 t = __floats2bfloat162_rn(a, b);   // x(lo)=a, y(hi)=b
    return *(uint32_t*)&t;
}

// ---------------- stage loader: A[128,32] hi/lo + B[128,32] hi/lo -------------
__device__ __forceinline__ void load_stage(uint32_t sb,
    const __nv_bfloat16* __restrict__ Ah, const __nv_bfloat16* __restrict__ Al,
    const __nv_bfloat16* __restrict__ Bh, const __nv_bfloat16* __restrict__ Bl,
    int m0, int n0, int k0, int tid)
{
#pragma unroll
    for (int r = 0; r < 2; ++r) {
        int c = tid + 256 * r;
        int row = c >> 2, jc = c & 3;
        uint32_t so = (uint32_t)(row * (RS * 2) + jc * 16);
        size_t ga = (size_t)(m0 + row) * GEMM_K + k0 + jc * 8;
        size_t gb = (size_t)(n0 + row) * GEMM_K + k0 + jc * 8;
        cp16(sb + AHI_OFF + so, Ah + ga);
        cp16(sb + ALO_OFF + so, Al + ga);
        cp16(sb + BHI_OFF + so, Bh + gb);
        cp16(sb + BLO_OFF + so, Bl + gb);
    }
}

// ---------------- GEMM: C[M,Ntot] = A @ B^T (bf16x3, fp32 accum) --------------
// 2 CTAs/SM: 80KB smem, <=128 regs. Optional fused bf16 hi/lo split outputs
// (Ch/Cl non-null -> also write bf16 split of C; removes a split_rm pass).
__global__ __launch_bounds__(256, 2)
void gemm_bf16x3(const __nv_bfloat16* __restrict__ Ah, const __nv_bfloat16* __restrict__ Al,
                 const __nv_bfloat16* __restrict__ Bh, const __nv_bfloat16* __restrict__ Bl,
                 float* __restrict__ C, __nv_bfloat16* __restrict__ Ch,
                 __nv_bfloat16* __restrict__ Cl, int Ntot)
{
    extern __shared__ char dynsm[];
    const uint32_t sbase = smem_u32(dynsm);
    const int tid = threadIdx.x;
    const int w = tid >> 5, lane = tid & 31;
    const int wm = w & 3, wn = w >> 2;
    const int m0 = blockIdx.y * BM, n0 = blockIdx.x * BN;

    float acc[2][8][4];
#pragma unroll
    for (int i = 0; i < 2; ++i)
#pragma unroll
        for (int j = 0; j < 8; ++j)
#pragma unroll
            for (int q = 0; q < 4; ++q) acc[i][j][q] = 0.0f;

    // prologue: stage 0
    load_stage(sbase, Ah, Al, Bh, Bl, m0, n0, 0, tid);
    CP_COMMIT();

    const uint32_t lrow = (lane & 15);
    const uint32_t lcol = (lane >> 4) * 16;

    for (int it = 0; it < NIT; ++it) {
        CP_WAIT0();           // only load(it) pending here
        __syncthreads();      // all warps done with the other buffer -> safe to refill
        const uint32_t sb = sbase + (uint32_t)(it & 1) * STAGE_B;

        if (it + 1 < NIT) {   // prefetch next stage; overlaps with compute below
            load_stage(sbase + (uint32_t)((it + 1) & 1) * STAGE_B,
                       Ah, Al, Bh, Bl, m0, n0, (it + 1) * BK, tid);
            CP_COMMIT();
        }

#pragma unroll
        for (int ks = 0; ks < 2; ++ks) {
            const uint32_t kb = (uint32_t)ks * 32 + lcol;
            uint32_t ah[2][4], al[2][4];
#pragma unroll
            for (int mi = 0; mi < 2; ++mi) {
                uint32_t ra = sb + (uint32_t)((wm * 32 + mi * 16 + lrow) * (RS * 2)) + kb;
                LDSM4(ah[mi], ra + AHI_OFF);
                LDSM4(al[mi], ra + ALO_OFF);
            }
#pragma unroll
            for (int ni = 0; ni < 4; ++ni) {
                uint32_t rb = sb + (uint32_t)((wn * 64 + ni * 16 + lrow) * (RS * 2)) + kb;
                uint32_t bh4[4], bl4[4];
                LDSM4(bh4, rb + BHI_OFF);
                LDSM4(bl4, rb + BLO_OFF);
#pragma unroll
                for (int mi = 0; mi < 2; ++mi)
#pragma unroll
                    for (int hf = 0; hf < 2; ++hf) {
                        int n8 = ni * 2 + hf;
                        MMA16816(acc[mi][n8], ah[mi], bh4[hf], bh4[hf + 2]);
                        MMA16816(acc[mi][n8], ah[mi], bl4[hf], bl4[hf + 2]);
                        MMA16816(acc[mi][n8], al[mi], bh4[hf], bh4[hf + 2]);
                    }
            }
        }
    }

    // epilogue: fp32 stores + optional fused bf16 hi/lo split stores
    const int crow = wm * 32 + (lane >> 2);
    const int ccol = wn * 64 + (lane & 3) * 2;
#pragma unroll
    for (int mi = 0; mi < 2; ++mi)
#pragma unroll
        for (int n8 = 0; n8 < 8; ++n8) {
            int r0 = m0 + crow + mi * 16;
            int cc = n0 + ccol + n8 * 8;
            float a0 = acc[mi][n8][0], a1 = acc[mi][n8][1];
            float a2 = acc[mi][n8][2], a3 = acc[mi][n8][3];
            *(float2*)(C + (size_t)r0 * Ntot + cc)       = make_float2(a0, a1);
            *(float2*)(C + (size_t)(r0 + 8) * Ntot + cc) = make_float2(a2, a3);
            if (Ch) {
                __nv_bfloat16 h0 = __float2bfloat16_rn(a0), h1 = __float2bfloat16_rn(a1);
                __nv_bfloat16 h2 = __float2bfloat16_rn(a2), h3 = __float2bfloat16_rn(a3);
                *(__nv_bfloat162*)(Ch + (size_t)r0 * Ntot + cc)       = __halves2bfloat162(h0, h1);
                *(__nv_bfloat162*)(Ch + (size_t)(r0 + 8) * Ntot + cc) = __halves2bfloat162(h2, h3);
                __nv_bfloat16 l0 = __float2bfloat16_rn(a0 - __bfloat162float(h0));
                __nv_bfloat16 l1 = __float2bfloat16_rn(a1 - __bfloat162float(h1));
                __nv_bfloat16 l2 = __float2bfloat16_rn(a2 - __bfloat162float(h2));
                __nv_bfloat16 l3 = __float2bfloat16_rn(a3 - __bfloat162float(h3));
                *(__nv_bfloat162*)(Cl + (size_t)r0 * Ntot + cc)       = __halves2bfloat162(l0, l1);
                *(__nv_bfloat162*)(Cl + (size_t)(r0 + 8) * Ntot + cc) = __halves2bfloat162(l2, l3);
            }
        }
}

// ---------------- fp32 -> bf16 hi/lo split (row-major; input X only) ----------
__global__ void split_rm(const float* __restrict__ in, __nv_bfloat16* __restrict__ oh,
                         __nv_bfloat16* __restrict__ ol, int n4)
{
    int i = blockIdx.x * blockDim.x + threadIdx.x;
    if (i >= n4) return;
    float4 v = ((const float4*)in)[i];
    __nv_bfloat16 h0 = __float2bfloat16_rn(v.x), h1 = __float2bfloat16_rn(v.y);
    __nv_bfloat16 h2 = __float2bfloat16_rn(v.z), h3 = __float2bfloat16_rn(v.w);
    __nv_bfloat16 l0 = __float2bfloat16_rn(v.x - __bfloat162float(h0));
    __nv_bfloat16 l1 = __float2bfloat16_rn(v.y - __bfloat162float(h1));
    __nv_bfloat16 l2 = __float2bfloat16_rn(v.z - __bfloat162float(h2));
    __nv_bfloat16 l3 = __float2bfloat16_rn(v.w - __bfloat162float(h3));
    ((__nv_bfloat162*)oh)[2 * i + 0] = __halves2bfloat162(h0, h1);
    ((__nv_bfloat162*)oh)[2 * i + 1] = __halves2bfloat162(h2, h3);
    ((__nv_bfloat162*)ol)[2 * i + 0] = __halves2bfloat162(l0, l1);
    ((__nv_bfloat162*)ol)[2 * i + 1] = __halves2bfloat162(l2, l3);
}

// ---------------- fp32 [2048,2048] -> transposed bf16 hi/lo (2 mats via z) ----
__global__ void split_tr2(const float* __restrict__ sA, __nv_bfloat16* __restrict__ hA,
                          __nv_bfloat16* __restrict__ lA,
                          const float* __restrict__ sB, __nv_bfloat16* __restrict__ hB,
                          __nv_bfloat16* __restrict__ lB)
{
    const float* in   = blockIdx.z ? sB : sA;
    __nv_bfloat16* oh = blockIdx.z ? hB : hA;
    __nv_bfloat16* ol = blockIdx.z ? lB : lA;
    __shared__ float t[32][33];
    int x = blockIdx.x * 32 + threadIdx.x;
#pragma unroll
    for (int j = 0; j < 4; ++j) {
        int y = blockIdx.y * 32 + threadIdx.y + j * 8;
        t[threadIdx.y + j * 8][threadIdx.x] = in[(size_t)y * 2048 + x];
    }
    __syncthreads();
    int x2 = blockIdx.y * 32 + threadIdx.x;
#pragma unroll
    for (int j = 0; j < 4; ++j) {
        int y2 = blockIdx.x * 32 + threadIdx.y + j * 8;
        float v = t[threadIdx.x][threadIdx.y + j * 8];
        __nv_bfloat16 h = __float2bfloat16_rn(v);
        __nv_bfloat16 l = __float2bfloat16_rn(v - __bfloat162float(h));
        oh[(size_t)y2 * 2048 + x2] = h;
        ol[(size_t)y2 * 2048 + x2] = l;
    }
}

// ---------------- block-mean gate keys ----------------------------------------
__global__ void kg_kernel() {
    int t = blockIdx.x * blockDim.x + threadIdx.x;
    if (t >= NB * HIDN) return;
    int n = t / HIDN;
    int c = t % HIDN;
    float sum = 0.0f;
    const float* kp = g_qkv + (size_t)(n * BLK) * (3 * HIDN) + HIDN + c;
#pragma unroll 8
    for (int i = 0; i < BLK; i++) sum += kp[(size_t)i * (3 * HIDN)];
    g_kgt[(size_t)c * NB + n] = sum * (1.0f / BLK);
}

// ---------------- gating + top-k -> per-(h,s) block bitmask -------------------
__global__ __launch_bounds__(128)
void gate_kernel() {
    int warp = (blockIdx.x * blockDim.x + threadIdx.x) >> 5;
    int lane = threadIdx.x & 31;
    if (warp >= NH * SEQ) return;
    int h = warp / SEQ;
    int s = warp % SEQ;

    const float* qrow = g_qkv + (size_t)s * (3 * HIDN) + h * HD;
    const float* kgp  = g_kgt + (size_t)h * HD * NB + lane;
    float score = 0.0f;
#pragma unroll 8
    for (int d = 0; d < HD; d++)
        score = fmaf(qrow[d], kgp[(size_t)d * NB], score);

    int qb = s >> 6;
    if (lane == qb)      score =  CUDART_INF_F;
    else if (lane > qb)  score = -CUDART_INF_F;

    float val = score;
    uint32_t mask = 0;
#pragma unroll
    for (int t = 0; t < TOPK; t++) {
        float v = val; int idx = lane;
#pragma unroll
        for (int off = 16; off; off >>= 1) {
            float ov = __shfl_xor_sync(0xffffffffu, v, off);
            int   oi = __shfl_xor_sync(0xffffffffu, idx, off);
            if (ov > v || (ov == v && oi < idx)) { v = ov; idx = oi; }
        }
        if (v != -CUDART_INF_F) mask |= (1u << idx);   // -inf picks fully causal-masked -> skip
        if (lane == idx) val = -CUDART_INF_F;
    }
    if (lane == 0) g_mask[(size_t)h * SEQ + s] = mask;
}

// ---------------- tensor-core block-sparse flash attention --------------------
// CTA = (query block qb, head h). 4 warps x 16 query rows. K/V blocks staged
// once into smem (bf16 hi/lo); S and PV via mma with bf16x3 compensation.
// Epilogue writes bf16 hi/lo of O directly (feeds gemm2; no split pass).
__global__ __launch_bounds__(128)
void attn_mma() {
    extern __shared__ char asmem[];
    __shared__ uint32_t s_qmask[64];
    __shared__ uint32_t s_union;
    const uint32_t F = 0xffffffffu;
    const int qb = blockIdx.x, h = blockIdx.y;
    const int tid = threadIdx.x, w = tid >> 5, lane = tid & 31;
    const uint32_t sb = smem_u32(asmem);
    const char* qh_b = (const char*)g_qkvh;
    const char* ql_b = (const char*)g_qkvl;
    const size_t GROW = 3 * HIDN * 2;               // global row bytes (12288)

    if (tid < 64) s_qmask[tid] = g_mask[(size_t)h * SEQ + qb * 64 + tid];
    __syncthreads();
    if (tid == 0) {
        uint32_t u = 0;
#pragma unroll
        for (int i = 0; i < 64; i++) u |= s_qmask[i];
        s_union = u;
    }

    // stage Q tile (hi/lo): rows qb*64 + j, cols h*128..h*128+127
#pragma unroll
    for (int i = tid; i < 1024; i += 128) {
        int row = i >> 4, c = i & 15;
        uint32_t dst = (uint32_t)(row * TSTR + c * 16);
        size_t src = (size_t)(qb * 64 + row) * GROW + (size_t)(h * HD) * 2 + c * 16;
        cp16(sb + AQH + dst, qh_b + src);
        cp16(sb + AQL + dst, ql_b + src);
    }
    CP_COMMIT(); CP_WAIT0();
    __syncthreads();

    const uint32_t um = s_union;
    const int r1 = lane >> 2;
    const int qloc1 = w * 16 + r1, qloc2 = qloc1 + 8;
    const uint32_t qm1 = s_qmask[qloc1], qm2 = s_qmask[qloc2];
    const uint32_t la = (lane & 15), lc = (lane >> 4) * 16;
    const int col2 = 2 * (lane & 3);

    float m1 = -1e30f, m2 = -1e30f, l1 = 0.0f, l2 = 0.0f;
    float O[16][4];
#pragma unroll
    for (int t = 0; t < 16; ++t)
#pragma unroll
        for (int q = 0; q < 4; ++q) O[t][q] = 0.0f;

    for (int b = 0; b <= qb; ++b) {
        if (!((um >> b) & 1u)) continue;
        __syncthreads();   // previous block's smem fully consumed
        // stage K,V (hi/lo)
#pragma unroll
        for (int i = tid; i < 1024; i += 128) {
            int row = i >> 4, c = i & 15;
            uint32_t dst = (uint32_t)(row * TSTR + c * 16);
            size_t gro = (size_t)(b * 64 + row) * GROW;
            size_t ko = gro + (size_t)(HIDN + h * HD) * 2 + c * 16;
            size_t vo = gro + (size_t)(2 * HIDN + h * HD) * 2 + c * 16;
            cp16(sb + AKH + dst, qh_b + ko);
            cp16(sb + AKL + dst, ql_b + ko);
            cp16(sb + AVH + dst, qh_b + vo);
            cp16(sb + AVL + dst, ql_b + vo);
        }
        CP_COMMIT(); CP_WAIT0();
        __syncthreads();

        // ---- S = Q @ K^T (bf16x3) ----
        float S[8][4];
#pragma unroll
        for (int t = 0; t < 8; ++t)
#pragma unroll
            for (int q = 0; q < 4; ++q) S[t][q] = 0.0f;

#pragma unroll
        for (int ks = 0; ks < 8; ++ks) {
            uint32_t qa = sb + AQH + (uint32_t)((w * 16 + la) * TSTR) + ks * 32 + lc;
            uint32_t qh4[4], ql4[4];
            LDSM4(qh4, qa);
            LDSM4(ql4, qa + (AQL - AQH));
#pragma unroll
            for (int jt = 0; jt < 4; ++jt) {
                uint32_t ka = sb + AKH + (uint32_t)((jt * 16 + la) * TSTR) + ks * 32 + lc;
                uint32_t kh4[4], kl4[4];
                LDSM4(kh4, ka);
                LDSM4(kl4, ka + (AKL - AKH));
                MMA16816(S[2 * jt],     qh4, kh4[0], kh4[2]);
                MMA16816(S[2 * jt],     qh4, kl4[0], kl4[2]);
                MMA16816(S[2 * jt],     ql4, kh4[0], kh4[2]);
                MMA16816(S[2 * jt + 1], qh4, kh4[1], kh4[3]);
                MMA16816(S[2 * jt + 1], qh4, kl4[1], kl4[3]);
                MMA16816(S[2 * jt + 1], ql4, kh4[1], kh4[3]);
            }
        }

        // ---- mask + scale (log2 domain) ----
        const bool self = (b == qb);
        const int lim1 = ((qm1 >> b) & 1u) ? (self ? qloc1 : 63) : -1;
        const int lim2 = ((qm2 >> b) & 1u) ? (self ? qloc2 : 63) : -1;
        float mx1 = -1e30f, mx2 = -1e30f;
#pragma unroll
        for (int t = 0; t < 8; ++t) {
            int j0 = t * 8 + col2, j1 = j0 + 1;
            S[t][0] = (j0 <= lim1) ? S[t][0] * SM_SCALE_L2 : -CUDART_INF_F;
            S[t][1] = (j1 <= lim1) ? S[t][1] * SM_SCALE_L2 : -CUDART_INF_F;
            S[t][2] = (j0 <= lim2) ? S[t][2] * SM_SCALE_L2 : -CUDART_INF_F;
            S[t][3] = (j1 <= lim2) ? S[t][3] * SM_SCALE_L2 : -CUDART_INF_F;
            mx1 = fmaxf(mx1, fmaxf(S[t][0], S[t][1]));
            mx2 = fmaxf(mx2, fmaxf(S[t][2], S[t][3]));
        }
        mx1 = fmaxf(mx1, __shfl_xor_sync(F, mx1, 1));
        mx1 = fmaxf(mx1, __shfl_xor_sync(F, mx1, 2));
        mx2 = fmaxf(mx2, __shfl_xor_sync(F, mx2, 1));
        mx2 = fmaxf(mx2, __shfl_xor_sync(F, mx2, 2));
        float mn1 = fmaxf(m1, mx1), mn2 = fmaxf(m2, mx2);
        float corr1 = ex2(m1 - mn1), corr2 = ex2(m2 - mn2);
        m1 = mn1; m2 = mn2;

        // ---- P = exp2(S - m), convert to bf16 hi/lo ----
        float rs1 = 0.0f, rs2 = 0.0f;
        uint32_t ph2[16], pl2[16];
#pragma unroll
        for (int t = 0; t < 8; ++t) {
            float e0 = ex2(S[t][0] - mn1), e1 = ex2(S[t][1] - mn1);
            float e2 = ex2(S[t][2] - mn2), e3 = ex2(S[t][3] - mn2);
            rs1 += e0 + e1; rs2 += e2 + e3;
            __nv_bfloat16 b0 = __float2bfloat16_rn(e0), b1 = __float2bfloat16_rn(e1);
            __nv_bfloat16 b2 = __float2bfloat16_rn(e2), b3 = __float2bfloat16_rn(e3);
            __nv_bfloat162 p01 = __halves2bfloat162(b0, b1);
            __nv_bfloat162 p23 = __halves2bfloat162(b2, b3);
            ph2[2 * t]     = *(uint32_t*)&p01;
            ph2[2 * t + 1] = *(uint32_t*)&p23;
            pl2[2 * t]     = pack_bf16f(e0 - __bfloat162float(b0), e1 - __bfloat162float(b1));
            pl2[2 * t + 1] = pack_bf16f(e2 - __bfloat162float(b2), e3 - __bfloat162float(b3));
        }
        rs1 += __shfl_xor_sync(F, rs1, 1); rs1 += __shfl_xor_sync(F, rs1, 2);
        rs2 += __shfl_xor_sync(F, rs2, 1); rs2 += __shfl_xor_sync(F, rs2, 2);
        l1 = l1 * corr1 + rs1;
        l2 = l2 * corr2 + rs2;

        // ---- rescale O, then O += P @ V (bf16x3) ----
#pragma unroll
        for (int t = 0; t < 16; ++t) {
            O[t][0] *= corr1; O[t][1] *= corr1;
            O[t][2] *= corr2; O[t][3] *= corr2;
        }
#pragma unroll
        for (int ks = 0; ks < 4; ++ks) {
            uint32_t ph[4] = { ph2[4 * ks], ph2[4 * ks + 1], ph2[4 * ks + 2], ph2[4 * ks + 3] };
            uint32_t pl[4] = { pl2[4 * ks], pl2[4 * ks + 1], pl2[4 * ks + 2], pl2[4 * ks + 3] };
#pragma unroll
            for (int dt = 0; dt < 8; ++dt) {
                uint32_t va = sb + AVH + (uint32_t)((ks * 16 + la) * TSTR) + dt * 32 + lc;
                uint32_t vh4[4], vl4[4];
                LDSM4T(vh4, va);
                LDSM4T(vl4, va + (AVL - AVH));
                MMA16816(O[2 * dt],     ph, vh4[0], vh4[1]);
                MMA16816(O[2 * dt],     ph, vl4[0], vl4[1]);
                MMA16816(O[2 * dt],     pl, vh4[0], vh4[1]);
                MMA16816(O[2 * dt + 1], ph, vh4[2], vh4[3]);
                MMA16816(O[2 * dt + 1], ph, vl4[2], vl4[3]);
                MMA16816(O[2 * dt + 1], pl, vh4[2], vh4[3]);
            }
        }
    }

    // ---- epilogue: O /= l, write bf16 hi/lo directly (gemm2 operands) ----
    float inv1 = 1.0f / l1, inv2 = 1.0f / l2;   // self diag guarantees l > 0
    const int srow1 = qb * 64 + qloc1, srow2 = srow1 + 8;
#pragma unroll
    for (int t = 0; t < 16; ++t) {
        int d = h * HD + t * 8 + col2;
        float a0 = O[t][0] * inv1, a1 = O[t][1] * inv1;
        float a2 = O[t][2] * inv2, a3 = O[t][3] * inv2;
        __nv_bfloat16 h0 = __float2bfloat16_rn(a0), h1 = __float2bfloat16_rn(a1);
        __nv_bfloat16 h2 = __float2bfloat16_rn(a2), h3 = __float2bfloat16_rn(a3);
        *(__nv_bfloat162*)(g_atth + (size_t)srow1 * HIDN + d) = __halves2bfloat162(h0, h1);
        *(__nv_bfloat162*)(g_atth + (size_t)srow2 * HIDN + d) = __halves2bfloat162(h2, h3);
        __nv_bfloat16 l0 = __float2bfloat16_rn(a0 - __bfloat162float(h0));
        __nv_bfloat16 l1b = __float2bfloat16_rn(a1 - __bfloat162float(h1));
        __nv_bfloat16 l2b = __float2bfloat16_rn(a2 - __bfloat162float(h2));
        __nv_bfloat16 l3 = __float2bfloat16_rn(a3 - __bfloat162float(h3));
        *(__nv_bfloat162*)(g_attl + (size_t)srow1 * HIDN + d) = __halves2bfloat162(l0, l1b);
        *(__nv_bfloat162*)(g_attl + (size_t)srow2 * HIDN + d) = __halves2bfloat162(l2b, l3);
    }
}

// ---------------- launch -----------------------------------------------------
extern "C" void kernel_launch(void* const* d_in, const int* in_sizes, int n_in,
                              void* d_out, int out_size) {
    (void)in_sizes; (void)n_in; (void)out_size;
    const float* x  = (const float*)d_in[0];
    const float* Wq = (const float*)d_in[1];
    const float* Wk = (const float*)d_in[2];
    const float* Wv = (const float*)d_in[3];
    const float* Wo = (const float*)d_in[4];
    float* out = (float*)d_out;

    __nv_bfloat16 *xh, *xl, *wth, *wtl, *woth, *wotl, *atth, *attl, *qkvh, *qkvl;
    float *qkv;
    cudaGetSymbolAddress((void**)&xh,   g_xh);
    cudaGetSymbolAddress((void**)&xl,   g_xl);
    cudaGetSymbolAddress((void**)&wth,  g_wth);
    cudaGetSymbolAddress((void**)&wtl,  g_wtl);
    cudaGetSymbolAddress((void**)&woth, g_woth);
    cudaGetSymbolAddress((void**)&wotl, g_wotl);
    cudaGetSymbolAddress((void**)&atth, g_atth);
    cudaGetSymbolAddress((void**)&attl, g_attl);
    cudaGetSymbolAddress((void**)&qkv,  g_qkv);
    cudaGetSymbolAddress((void**)&qkvh, g_qkvh);
    cudaGetSymbolAddress((void**)&qkvl, g_qkvl);

    cudaFuncSetAttribute(gemm_bf16x3, cudaFuncAttributeMaxDynamicSharedMemorySize, SMEM_DYN);
    cudaFuncSetAttribute(attn_mma,    cudaFuncAttributeMaxDynamicSharedMemorySize, ATT_SMEM);

    const int n4x = SEQ * HIDN / 4;
    // launch order keeps gemm1 at kernel slot 4 = the ncu capture slot
    split_rm<<<(n4x + 255) / 256, 256>>>(x, xh, xl, n4x);
    dim3 tb(32, 8);
    split_tr2<<<dim3(64, 64, 2), tb>>>(Wq, wth, wtl,
                                       Wk, wth + HIDN * HIDN, wtl + HIDN * HIDN);
    split_tr2<<<dim3(64, 64, 2), tb>>>(Wv, wth + 2 * HIDN * HIDN, wtl + 2 * HIDN * HIDN,
                                       Wo, woth, wotl);

    // gemm1: fused epilogue writes qkv fp32 + bf16 hi/lo splits
    gemm_bf16x3<<<dim3(3 * HIDN / BN, SEQ / BM), 256, SMEM_DYN>>>(
        xh, xl, wth, wtl, qkv, qkvh, qkvl, 3 * HIDN);

    kg_kernel<<<(NB * HIDN + 255) / 256, 256>>>();
    gate_kernel<<<(NH * SEQ) / 4, 128>>>();
    attn_mma<<<dim3(NB, NH), 128, ATT_SMEM>>>();

    // gemm2: plain fp32 output (final result)
    gemm_bf16x3<<<dim3(HIDN / BN, SEQ / BM), 256, SMEM_DYN>>>(
        atth, attl, woth, wotl, out, nullptr, nullptr, HIDN);
}

// round 17
// speedup vs baseline: 1.0326x; 1.0059x over previous
#include <cuda_runtime.h>
#include <cuda_bf16.h>
#include <math_constants.h>
#include <cstdint>

#define SEQ   2048
#define HIDN  2048
#define NH    16
#define HD    128
#define NB    32
#define BLK   64
#define TOPK  8
#define SM_SCALE 0.08838834764831845f
// sm_scale * log2(e): scores kept in log2 domain for exp2
#define SM_SCALE_L2 0.1275208126606169f

// ---------------- GEMM config (mma.sync bf16, bf16x3 split) -------------------
#define BM 128
#define BN 128
#define BK 32
#define GEMM_K 2048
#define NIT (GEMM_K / BK)      // 64
#define STAGES 2               // 2-stage prefetch -> 80KB smem -> 2 CTAs/SM
#define RS 40                  // smem row stride in bf16 elems (80 B, pad for ldmatrix)
#define AHI_OFF 0
#define ALO_OFF (BM * RS * 2)          // 10240
#define BHI_OFF (2 * BM * RS * 2)      // 20480
#define BLO_OFF (3 * BM * RS * 2)      // 30720
#define STAGE_B (4 * BM * RS * 2)      // 40960
#define SMEM_DYN (STAGES * STAGE_B)    // 81920

// ---------------- attention smem layout (bf16 tiles, 272B row stride) ----------
#define TSTR 272                        // 64-row tile: 64*272 = 17408 B
#define TILE_B 17408
#define AQH 0
#define AQL (1 * TILE_B)
#define AKH (2 * TILE_B)
#define AKL (3 * TILE_B)
#define AVH (4 * TILE_B)
#define AVL (5 * TILE_B)
#define ATT_SMEM (6 * TILE_B)           // 104448 (x2 CTAs = 208896 <= 227KB)

// ---------------- scratch (static __device__, allocation-free) ----------------
__device__ __nv_bfloat16 g_xh[SEQ * HIDN];
__device__ __nv_bfloat16 g_xl[SEQ * HIDN];
__device__ __nv_bfloat16 g_wth[3 * HIDN * HIDN];   // (Wq|Wk|Wv)^T rows: [6144][2048]
__device__ __nv_bfloat16 g_wtl[3 * HIDN * HIDN];
__device__ __nv_bfloat16 g_woth[HIDN * HIDN];      // Wo^T [2048][2048]
__device__ __nv_bfloat16 g_wotl[HIDN * HIDN];
__device__ float g_qkv[SEQ * 3 * HIDN];            // [s][q|k|v], row stride 6144
__device__ __nv_bfloat16 g_qkvh[SEQ * 3 * HIDN];   // bf16 hi split of g_qkv
__device__ __nv_bfloat16 g_qkvl[SEQ * 3 * HIDN];   // bf16 lo split
__device__ __nv_bfloat16 g_atth[SEQ * HIDN];       // attention out, bf16 hi
__device__ __nv_bfloat16 g_attl[SEQ * HIDN];       // attention out, bf16 lo
__device__ float g_kgt[NH * HD * NB];
__device__ uint32_t g_mask[NH * SEQ];              // selected-block bitmask per (h,s)

// ---------------- PTX helpers (sm_80-baseline only: no tcgen05) ---------------
__device__ __forceinline__ uint32_t smem_u32(const void* p) {
    uint32_t a;
    asm("{ .reg .u64 t; cvta.to.shared.u64 t, %1; cvt.u32.u64 %0, t; }" : "=r"(a) : "l"(p));
    return a;
}
__device__ __forceinline__ void cp16(uint32_t dst, const void* src) {
    asm volatile("cp.async.cg.shared.global [%0], [%1], 16;" :: "r"(dst), "l"(src) : "memory");
}
#define CP_COMMIT() asm volatile("cp.async.commit_group;" ::: "memory")
#define CP_WAIT0()  asm volatile("cp.async.wait_group 0;" ::: "memory")

#define LDSM4(R, a) \
    asm volatile("ldmatrix.sync.aligned.m8n8.x4.shared.b16 {%0,%1,%2,%3}, [%4];" \
                 : "=r"((R)[0]), "=r"((R)[1]), "=r"((R)[2]), "=r"((R)[3]) : "r"(a))
#define LDSM4T(R, a) \
    asm volatile("ldmatrix.sync.aligned.m8n8.x4.trans.shared.b16 {%0,%1,%2,%3}, [%4];" \
                 : "=r"((R)[0]), "=r"((R)[1]), "=r"((R)[2]), "=r"((R)[3]) : "r"(a))

#define MMA16816(D, A, B0, B1) \
    asm volatile("mma.sync.aligned.m16n8k16.row.col.f32.bf16.bf16.f32 " \
                 "{%0,%1,%2,%3}, {%4,%5,%6,%7}, {%8,%9}, {%0,%1,%2,%3};" \
                 : "+f"((D)[0]), "+f"((D)[1]), "+f"((D)[2]), "+f"((D)[3]) \
                 : "r"((A)[0]), "r"((A)[1]), "r"((A)[2]), "r"((A)[3]), "r"(B0), "r"(B1))

__device__ __forceinline__ float ex2(float x) {
    float r; asm("ex2.approx.f32 %0, %1;" : "=f"(r) : "f"(x)); return r;
}
__device__ __forceinline__ uint32_t pack_bf16f(float a, float b) {
    __nv_bfloat162 t = __floats2bfloat162_rn(a, b);   // x(lo)=a, y(hi)=b
    return *(uint32_t*)&t;
}

// ---------------- stage loader: A[128,32] hi/lo + B[128,32] hi/lo -------------
__device__ __forceinline__ void load_stage(uint32_t sb,
    const __nv_bfloat16* __restrict__ Ah, const __nv_bfloat16* __restrict__ Al,
    const __nv_bfloat16* __restrict__ Bh, const __nv_bfloat16* __restrict__ Bl,
    int m0, int n0, int k0, int tid)
{
#pragma unroll
    for (int r = 0; r < 2; ++r) {
        int c = tid + 256 * r;
        int row = c >> 2, jc = c & 3;
        uint32_t so = (uint32_t)(row * (RS * 2) + jc * 16);
        size_t ga = (size_t)(m0 + row) * GEMM_K + k0 + jc * 8;
        size_t gb = (size_t)(n0 + row) * GEMM_K + k0 + jc * 8;
        cp16(sb + AHI_OFF + so, Ah + ga);
        cp16(sb + ALO_OFF + so, Al + ga);
        cp16(sb + BHI_OFF + so, Bh + gb);
        cp16(sb + BLO_OFF + so, Bl + gb);
    }
}

// ---------------- GEMM: C[M,Ntot] = A @ B^T (bf16x3, fp32 accum) --------------
// 2 CTAs/SM: 80KB smem, <=128 regs. Optional fused bf16 hi/lo split outputs.
__global__ __launch_bounds__(256, 2)
void gemm_bf16x3(const __nv_bfloat16* __restrict__ Ah, const __nv_bfloat16* __restrict__ Al,
                 const __nv_bfloat16* __restrict__ Bh, const __nv_bfloat16* __restrict__ Bl,
                 float* __restrict__ C, __nv_bfloat16* __restrict__ Ch,
                 __nv_bfloat16* __restrict__ Cl, int Ntot)
{
    extern __shared__ char dynsm[];
    const uint32_t sbase = smem_u32(dynsm);
    const int tid = threadIdx.x;
    const int w = tid >> 5, lane = tid & 31;
    const int wm = w & 3, wn = w >> 2;
    const int m0 = blockIdx.y * BM, n0 = blockIdx.x * BN;

    float acc[2][8][4];
#pragma unroll
    for (int i = 0; i < 2; ++i)
#pragma unroll
        for (int j = 0; j < 8; ++j)
#pragma unroll
            for (int q = 0; q < 4; ++q) acc[i][j][q] = 0.0f;

    // prologue: stage 0
    load_stage(sbase, Ah, Al, Bh, Bl, m0, n0, 0, tid);
    CP_COMMIT();

    const uint32_t lrow = (lane & 15);
    const uint32_t lcol = (lane >> 4) * 16;

    for (int it = 0; it < NIT; ++it) {
        CP_WAIT0();           // only load(it) pending here
        __syncthreads();      // all warps done with the other buffer -> safe to refill
        const uint32_t sb = sbase + (uint32_t)(it & 1) * STAGE_B;

        if (it + 1 < NIT) {   // prefetch next stage; overlaps with compute below
            load_stage(sbase + (uint32_t)((it + 1) & 1) * STAGE_B,
                       Ah, Al, Bh, Bl, m0, n0, (it + 1) * BK, tid);
            CP_COMMIT();
        }

#pragma unroll
        for (int ks = 0; ks < 2; ++ks) {
            const uint32_t kb = (uint32_t)ks * 32 + lcol;
            uint32_t ah[2][4], al[2][4];
#pragma unroll
            for (int mi = 0; mi < 2; ++mi) {
                uint32_t ra = sb + (uint32_t)((wm * 32 + mi * 16 + lrow) * (RS * 2)) + kb;
                LDSM4(ah[mi], ra + AHI_OFF);
                LDSM4(al[mi], ra + ALO_OFF);
            }
#pragma unroll
            for (int ni = 0; ni < 4; ++ni) {
                uint32_t rb = sb + (uint32_t)((wn * 64 + ni * 16 + lrow) * (RS * 2)) + kb;
                uint32_t bh4[4], bl4[4];
                LDSM4(bh4, rb + BHI_OFF);
                LDSM4(bl4, rb + BLO_OFF);
#pragma unroll
                for (int mi = 0; mi < 2; ++mi)
#pragma unroll
                    for (int hf = 0; hf < 2; ++hf) {
                        int n8 = ni * 2 + hf;
                        MMA16816(acc[mi][n8], ah[mi], bh4[hf], bh4[hf + 2]);
                        MMA16816(acc[mi][n8], ah[mi], bl4[hf], bl4[hf + 2]);
                        MMA16816(acc[mi][n8], al[mi], bh4[hf], bh4[hf + 2]);
                    }
            }
        }
    }

    // epilogue: fp32 stores + optional fused bf16 hi/lo split stores
    const int crow = wm * 32 + (lane >> 2);
    const int ccol = wn * 64 + (lane & 3) * 2;
#pragma unroll
    for (int mi = 0; mi < 2; ++mi)
#pragma unroll
        for (int n8 = 0; n8 < 8; ++n8) {
            int r0 = m0 + crow + mi * 16;
            int cc = n0 + ccol + n8 * 8;
            float a0 = acc[mi][n8][0], a1 = acc[mi][n8][1];
            float a2 = acc[mi][n8][2], a3 = acc[mi][n8][3];
            *(float2*)(C + (size_t)r0 * Ntot + cc)       = make_float2(a0, a1);
            *(float2*)(C + (size_t)(r0 + 8) * Ntot + cc) = make_float2(a2, a3);
            if (Ch) {
                __nv_bfloat16 h0 = __float2bfloat16_rn(a0), h1 = __float2bfloat16_rn(a1);
                __nv_bfloat16 h2 = __float2bfloat16_rn(a2), h3 = __float2bfloat16_rn(a3);
                *(__nv_bfloat162*)(Ch + (size_t)r0 * Ntot + cc)       = __halves2bfloat162(h0, h1);
                *(__nv_bfloat162*)(Ch + (size_t)(r0 + 8) * Ntot + cc) = __halves2bfloat162(h2, h3);
                __nv_bfloat16 l0 = __float2bfloat16_rn(a0 - __bfloat162float(h0));
                __nv_bfloat16 l1 = __float2bfloat16_rn(a1 - __bfloat162float(h1));
                __nv_bfloat16 l2 = __float2bfloat16_rn(a2 - __bfloat162float(h2));
                __nv_bfloat16 l3 = __float2bfloat16_rn(a3 - __bfloat162float(h3));
                *(__nv_bfloat162*)(Cl + (size_t)r0 * Ntot + cc)       = __halves2bfloat162(l0, l1);
                *(__nv_bfloat162*)(Cl + (size_t)(r0 + 8) * Ntot + cc) = __halves2bfloat162(l2, l3);
            }
        }
}

// ---------------- fp32 -> bf16 hi/lo split (row-major; input X only) ----------
__global__ void split_rm(const float* __restrict__ in, __nv_bfloat16* __restrict__ oh,
                         __nv_bfloat16* __restrict__ ol, int n4)
{
    int i = blockIdx.x * blockDim.x + threadIdx.x;
    if (i >= n4) return;
    float4 v = ((const float4*)in)[i];
    __nv_bfloat16 h0 = __float2bfloat16_rn(v.x), h1 = __float2bfloat16_rn(v.y);
    __nv_bfloat16 h2 = __float2bfloat16_rn(v.z), h3 = __float2bfloat16_rn(v.w);
    __nv_bfloat16 l0 = __float2bfloat16_rn(v.x - __bfloat162float(h0));
    __nv_bfloat16 l1 = __float2bfloat16_rn(v.y - __bfloat162float(h1));
    __nv_bfloat16 l2 = __float2bfloat16_rn(v.z - __bfloat162float(h2));
    __nv_bfloat16 l3 = __float2bfloat16_rn(v.w - __bfloat162float(h3));
    ((__nv_bfloat162*)oh)[2 * i + 0] = __halves2bfloat162(h0, h1);
    ((__nv_bfloat162*)oh)[2 * i + 1] = __halves2bfloat162(h2, h3);
    ((__nv_bfloat162*)ol)[2 * i + 0] = __halves2bfloat162(l0, l1);
    ((__nv_bfloat162*)ol)[2 * i + 1] = __halves2bfloat162(l2, l3);
}

// ---------------- fp32 [2048,2048] -> transposed bf16 hi/lo (2 mats via z) ----
__global__ void split_tr2(const float* __restrict__ sA, __nv_bfloat16* __restrict__ hA,
                          __nv_bfloat16* __restrict__ lA,
                          const float* __restrict__ sB, __nv_bfloat16* __restrict__ hB,
                          __nv_bfloat16* __restrict__ lB)
{
    const float* in   = blockIdx.z ? sB : sA;
    __nv_bfloat16* oh = blockIdx.z ? hB : hA;
    __nv_bfloat16* ol = blockIdx.z ? lB : lA;
    __shared__ float t[32][33];
    int x = blockIdx.x * 32 + threadIdx.x;
#pragma unroll
    for (int j = 0; j < 4; ++j) {
        int y = blockIdx.y * 32 + threadIdx.y + j * 8;
        t[threadIdx.y + j * 8][threadIdx.x] = in[(size_t)y * 2048 + x];
    }
    __syncthreads();
    int x2 = blockIdx.y * 32 + threadIdx.x;
#pragma unroll
    for (int j = 0; j < 4; ++j) {
        int y2 = blockIdx.x * 32 + threadIdx.y + j * 8;
        float v = t[threadIdx.x][threadIdx.y + j * 8];
        __nv_bfloat16 h = __float2bfloat16_rn(v);
        __nv_bfloat16 l = __float2bfloat16_rn(v - __bfloat162float(h));
        oh[(size_t)y2 * 2048 + x2] = h;
        ol[(size_t)y2 * 2048 + x2] = l;
    }
}

// ---------------- block-mean gate keys ----------------------------------------
__global__ void kg_kernel() {
    int t = blockIdx.x * blockDim.x + threadIdx.x;
    if (t >= NB * HIDN) return;
    int n = t / HIDN;
    int c = t % HIDN;
    float sum = 0.0f;
    const float* kp = g_qkv + (size_t)(n * BLK) * (3 * HIDN) + HIDN + c;
#pragma unroll 8
    for (int i = 0; i < BLK; i++) sum += kp[(size_t)i * (3 * HIDN)];
    g_kgt[(size_t)c * NB + n] = sum * (1.0f / BLK);
}

// ---------------- gating + top-k -> per-(h,s) block bitmask -------------------
__global__ __launch_bounds__(128)
void gate_kernel() {
    int warp = (blockIdx.x * blockDim.x + threadIdx.x) >> 5;
    int lane = threadIdx.x & 31;
    if (warp >= NH * SEQ) return;
    int h = warp / SEQ;
    int s = warp % SEQ;

    const float* qrow = g_qkv + (size_t)s * (3 * HIDN) + h * HD;
    const float* kgp  = g_kgt + (size_t)h * HD * NB + lane;
    float score = 0.0f;
#pragma unroll 8
    for (int d = 0; d < HD; d++)
        score = fmaf(qrow[d], kgp[(size_t)d * NB], score);

    int qb = s >> 6;
    if (lane == qb)      score =  CUDART_INF_F;
    else if (lane > qb)  score = -CUDART_INF_F;

    float val = score;
    uint32_t mask = 0;
#pragma unroll
    for (int t = 0; t < TOPK; t++) {
        float v = val; int idx = lane;
#pragma unroll
        for (int off = 16; off; off >>= 1) {
            float ov = __shfl_xor_sync(0xffffffffu, v, off);
            int   oi = __shfl_xor_sync(0xffffffffu, idx, off);
            if (ov > v || (ov == v && oi < idx)) { v = ov; idx = oi; }
        }
        if (v != -CUDART_INF_F) mask |= (1u << idx);   // -inf picks fully causal-masked -> skip
        if (lane == idx) val = -CUDART_INF_F;
    }
    if (lane == 0) g_mask[(size_t)h * SEQ + s] = mask;
}

// ---------------- tensor-core block-sparse flash attention --------------------
// CTA = (query block qb, head h). 4 warps x 16 query rows. K/V blocks staged
// once into smem (bf16 hi/lo); S and PV via mma with bf16x3 compensation.
// Per-warp block skip: if none of the warp's 16 queries selects block b, the
// whole S/softmax/PV section is a provable no-op (all lims=-1 -> e=0, corr=1)
// and is skipped. Staging + both syncthreads remain CTA-wide.
__global__ __launch_bounds__(128, 2)
void attn_mma() {
    extern __shared__ char asmem[];
    __shared__ uint32_t s_qmask[64];
    __shared__ uint32_t s_union;
    const uint32_t F = 0xffffffffu;
    const int qb = blockIdx.x, h = blockIdx.y;
    const int tid = threadIdx.x, w = tid >> 5, lane = tid & 31;
    const uint32_t sb = smem_u32(asmem);
    const char* qh_b = (const char*)g_qkvh;
    const char* ql_b = (const char*)g_qkvl;
    const size_t GROW = 3 * HIDN * 2;               // global row bytes (12288)

    if (tid < 64) s_qmask[tid] = g_mask[(size_t)h * SEQ + qb * 64 + tid];
    __syncthreads();
    if (tid == 0) {
        uint32_t u = 0;
#pragma unroll
        for (int i = 0; i < 64; i++) u |= s_qmask[i];
        s_union = u;
    }

    // stage Q tile (hi/lo): rows qb*64 + j, cols h*128..h*128+127
#pragma unroll
    for (int i = tid; i < 1024; i += 128) {
        int row = i >> 4, c = i & 15;
        uint32_t dst = (uint32_t)(row * TSTR + c * 16);
        size_t src = (size_t)(qb * 64 + row) * GROW + (size_t)(h * HD) * 2 + c * 16;
        cp16(sb + AQH + dst, qh_b + src);
        cp16(sb + AQL + dst, ql_b + src);
    }
    CP_COMMIT(); CP_WAIT0();
    __syncthreads();

    const uint32_t um = s_union;
    // per-warp union of this warp's 16 query masks (rows w*16 .. w*16+15)
    uint32_t wq = s_qmask[w * 16 + (lane & 15)];
    wq |= __shfl_xor_sync(F, wq, 1);
    wq |= __shfl_xor_sync(F, wq, 2);
    wq |= __shfl_xor_sync(F, wq, 4);
    wq |= __shfl_xor_sync(F, wq, 8);
    wq |= __shfl_xor_sync(F, wq, 16);

    const int r1 = lane >> 2;
    const int qloc1 = w * 16 + r1, qloc2 = qloc1 + 8;
    const uint32_t qm1 = s_qmask[qloc1], qm2 = s_qmask[qloc2];
    const uint32_t la = (lane & 15), lc = (lane >> 4) * 16;
    const int col2 = 2 * (lane & 3);

    float m1 = -1e30f, m2 = -1e30f, l1 = 0.0f, l2 = 0.0f;
    float O[16][4];
#pragma unroll
    for (int t = 0; t < 16; ++t)
#pragma unroll
        for (int q = 0; q < 4; ++q) O[t][q] = 0.0f;

    for (int b = 0; b <= qb; ++b) {
        if (!((um >> b) & 1u)) continue;
        __syncthreads();   // previous block's smem fully consumed
        // stage K,V (hi/lo) — CTA-wide regardless of per-warp need
#pragma unroll
        for (int i = tid; i < 1024; i += 128) {
            int row = i >> 4, c = i & 15;
            uint32_t dst = (uint32_t)(row * TSTR + c * 16);
            size_t gro = (size_t)(b * 64 + row) * GROW;
            size_t ko = gro + (size_t)(HIDN + h * HD) * 2 + c * 16;
            size_t vo = gro + (size_t)(2 * HIDN + h * HD) * 2 + c * 16;
            cp16(sb + AKH + dst, qh_b + ko);
            cp16(sb + AKL + dst, ql_b + ko);
            cp16(sb + AVH + dst, qh_b + vo);
            cp16(sb + AVL + dst, ql_b + vo);
        }
        CP_COMMIT(); CP_WAIT0();
        __syncthreads();

        if (!((wq >> b) & 1u)) continue;   // warp-uniform: no query here needs b

        // ---- S = Q @ K^T (bf16x3) ----
        float S[8][4];
#pragma unroll
        for (int t = 0; t < 8; ++t)
#pragma unroll
            for (int q = 0; q < 4; ++q) S[t][q] = 0.0f;

#pragma unroll
        for (int ks = 0; ks < 8; ++ks) {
            uint32_t qa = sb + AQH + (uint32_t)((w * 16 + la) * TSTR) + ks * 32 + lc;
            uint32_t qh4[4], ql4[4];
            LDSM4(qh4, qa);
            LDSM4(ql4, qa + (AQL - AQH));
#pragma unroll
            for (int jt = 0; jt < 4; ++jt) {
                uint32_t ka = sb + AKH + (uint32_t)((jt * 16 + la) * TSTR) + ks * 32 + lc;
                uint32_t kh4[4], kl4[4];
                LDSM4(kh4, ka);
                LDSM4(kl4, ka + (AKL - AKH));
                MMA16816(S[2 * jt],     qh4, kh4[0], kh4[2]);
                MMA16816(S[2 * jt],     qh4, kl4[0], kl4[2]);
                MMA16816(S[2 * jt],     ql4, kh4[0], kh4[2]);
                MMA16816(S[2 * jt + 1], qh4, kh4[1], kh4[3]);
                MMA16816(S[2 * jt + 1], qh4, kl4[1], kl4[3]);
                MMA16816(S[2 * jt + 1], ql4, kh4[1], kh4[3]);
            }
        }

        // ---- mask + scale (log2 domain) ----
        const bool self = (b == qb);
        const int lim1 = ((qm1 >> b) & 1u) ? (self ? qloc1 : 63) : -1;
        const int lim2 = ((qm2 >> b) & 1u) ? (self ? qloc2 : 63) : -1;
        float mx1 = -1e30f, mx2 = -1e30f;
#pragma unroll
        for (int t = 0; t < 8; ++t) {
            int j0 = t * 8 + col2, j1 = j0 + 1;
            S[t][0] = (j0 <= lim1) ? S[t][0] * SM_SCALE_L2 : -CUDART_INF_F;
            S[t][1] = (j1 <= lim1) ? S[t][1] * SM_SCALE_L2 : -CUDART_INF_F;
            S[t][2] = (j0 <= lim2) ? S[t][2] * SM_SCALE_L2 : -CUDART_INF_F;
            S[t][3] = (j1 <= lim2) ? S[t][3] * SM_SCALE_L2 : -CUDART_INF_F;
            mx1 = fmaxf(mx1, fmaxf(S[t][0], S[t][1]));
            mx2 = fmaxf(mx2, fmaxf(S[t][2], S[t][3]));
        }
        mx1 = fmaxf(mx1, __shfl_xor_sync(F, mx1, 1));
        mx1 = fmaxf(mx1, __shfl_xor_sync(F, mx1, 2));
        mx2 = fmaxf(mx2, __shfl_xor_sync(F, mx2, 1));
        mx2 = fmaxf(mx2, __shfl_xor_sync(F, mx2, 2));
        float mn1 = fmaxf(m1, mx1), mn2 = fmaxf(m2, mx2);
        float corr1 = ex2(m1 - mn1), corr2 = ex2(m2 - mn2);
        m1 = mn1; m2 = mn2;

        // ---- P = exp2(S - m), convert to bf16 hi/lo ----
        float rs1 = 0.0f, rs2 = 0.0f;
        uint32_t ph2[16], pl2[16];
#pragma unroll
        for (int t = 0; t < 8; ++t) {
            float e0 = ex2(S[t][0] - mn1), e1 = ex2(S[t][1] - mn1);
            float e2 = ex2(S[t][2] - mn2), e3 = ex2(S[t][3] - mn2);
            rs1 += e0 + e1; rs2 += e2 + e3;
            __nv_bfloat16 b0 = __float2bfloat16_rn(e0), b1 = __float2bfloat16_rn(e1);
            __nv_bfloat16 b2 = __float2bfloat16_rn(e2), b3 = __float2bfloat16_rn(e3);
            __nv_bfloat162 p01 = __halves2bfloat162(b0, b1);
            __nv_bfloat162 p23 = __halves2bfloat162(b2, b3);
            ph2[2 * t]     = *(uint32_t*)&p01;
            ph2[2 * t + 1] = *(uint32_t*)&p23;
            pl2[2 * t]     = pack_bf16f(e0 - __bfloat162float(b0), e1 - __bfloat162float(b1));
            pl2[2 * t + 1] = pack_bf16f(e2 - __bfloat162float(b2), e3 - __bfloat162float(b3));
        }
        rs1 += __shfl_xor_sync(F, rs1, 1); rs1 += __shfl_xor_sync(F, rs1, 2);
        rs2 += __shfl_xor_sync(F, rs2, 1); rs2 += __shfl_xor_sync(F, rs2, 2);
        l1 = l1 * corr1 + rs1;
        l2 = l2 * corr2 + rs2;

        // ---- rescale O, then O += P @ V (bf16x3) ----
#pragma unroll
        for (int t = 0; t < 16; ++t) {
            O[t][0] *= corr1; O[t][1] *= corr1;
            O[t][2] *= corr2; O[t][3] *= corr2;
        }
#pragma unroll
        for (int ks = 0; ks < 4; ++ks) {
            uint32_t ph[4] = { ph2[4 * ks], ph2[4 * ks + 1], ph2[4 * ks + 2], ph2[4 * ks + 3] };
            uint32_t pl[4] = { pl2[4 * ks], pl2[4 * ks + 1], pl2[4 * ks + 2], pl2[4 * ks + 3] };
#pragma unroll
            for (int dt = 0; dt < 8; ++dt) {
                uint32_t va = sb + AVH + (uint32_t)((ks * 16 + la) * TSTR) + dt * 32 + lc;
                uint32_t vh4[4], vl4[4];
                LDSM4T(vh4, va);
                LDSM4T(vl4, va + (AVL - AVH));
                MMA16816(O[2 * dt],     ph, vh4[0], vh4[1]);
                MMA16816(O[2 * dt],     ph, vl4[0], vl4[1]);
                MMA16816(O[2 * dt],     pl, vh4[0], vh4[1]);
                MMA16816(O[2 * dt + 1], ph, vh4[2], vh4[3]);
                MMA16816(O[2 * dt + 1], ph, vl4[2], vl4[3]);
                MMA16816(O[2 * dt + 1], pl, vh4[2], vh4[3]);
            }
        }
    }

    // ---- epilogue: O /= l, write bf16 hi/lo directly (gemm2 operands) ----
    float inv1 = 1.0f / l1, inv2 = 1.0f / l2;   // self diag guarantees l > 0
    const int srow1 = qb * 64 + qloc1, srow2 = srow1 + 8;
#pragma unroll
    for (int t = 0; t < 16; ++t) {
        int d = h * HD + t * 8 + col2;
        float a0 = O[t][0] * inv1, a1 = O[t][1] * inv1;
        float a2 = O[t][2] * inv2, a3 = O[t][3] * inv2;
        __nv_bfloat16 h0 = __float2bfloat16_rn(a0), h1 = __float2bfloat16_rn(a1);
        __nv_bfloat16 h2 = __float2bfloat16_rn(a2), h3 = __float2bfloat16_rn(a3);
        *(__nv_bfloat162*)(g_atth + (size_t)srow1 * HIDN + d) = __halves2bfloat162(h0, h1);
        *(__nv_bfloat162*)(g_atth + (size_t)srow2 * HIDN + d) = __halves2bfloat162(h2, h3);
        __nv_bfloat16 l0 = __float2bfloat16_rn(a0 - __bfloat162float(h0));
        __nv_bfloat16 l1b = __float2bfloat16_rn(a1 - __bfloat162float(h1));
        __nv_bfloat16 l2b = __float2bfloat16_rn(a2 - __bfloat162float(h2));
        __nv_bfloat16 l3 = __float2bfloat16_rn(a3 - __bfloat162float(h3));
        *(__nv_bfloat162*)(g_attl + (size_t)srow1 * HIDN + d) = __halves2bfloat162(l0, l1b);
        *(__nv_bfloat162*)(g_attl + (size_t)srow2 * HIDN + d) = __halves2bfloat162(l2b, l3);
    }
}

// ---------------- launch -----------------------------------------------------
extern "C" void kernel_launch(void* const* d_in, const int* in_sizes, int n_in,
                              void* d_out, int out_size) {
    (void)in_sizes; (void)n_in; (void)out_size;
    const float* x  = (const float*)d_in[0];
    const float* Wq = (const float*)d_in[1];
    const float* Wk = (const float*)d_in[2];
    const float* Wv = (const float*)d_in[3];
    const float* Wo = (const float*)d_in[4];
    float* out = (float*)d_out;

    __nv_bfloat16 *xh, *xl, *wth, *wtl, *woth, *wotl, *atth, *attl, *qkvh, *qkvl;
    float *qkv;
    cudaGetSymbolAddress((void**)&xh,   g_xh);
    cudaGetSymbolAddress((void**)&xl,   g_xl);
    cudaGetSymbolAddress((void**)&wth,  g_wth);
    cudaGetSymbolAddress((void**)&wtl,  g_wtl);
    cudaGetSymbolAddress((void**)&woth, g_woth);
    cudaGetSymbolAddress((void**)&wotl, g_wotl);
    cudaGetSymbolAddress((void**)&atth, g_atth);
    cudaGetSymbolAddress((void**)&attl, g_attl);
    cudaGetSymbolAddress((void**)&qkv,  g_qkv);
    cudaGetSymbolAddress((void**)&qkvh, g_qkvh);
    cudaGetSymbolAddress((void**)&qkvl, g_qkvl);

    cudaFuncSetAttribute(gemm_bf16x3, cudaFuncAttributeMaxDynamicSharedMemorySize, SMEM_DYN);
    cudaFuncSetAttribute(attn_mma,    cudaFuncAttributeMaxDynamicSharedMemorySize, ATT_SMEM);

    const int n4x = SEQ * HIDN / 4;
    // launch order keeps gemm1 at kernel slot 4 = the ncu capture slot
    split_rm<<<(n4x + 255) / 256, 256>>>(x, xh, xl, n4x);
    dim3 tb(32, 8);
    split_tr2<<<dim3(64, 64, 2), tb>>>(Wq, wth, wtl,
                                       Wk, wth + HIDN * HIDN, wtl + HIDN * HIDN);
    split_tr2<<<dim3(64, 64, 2), tb>>>(Wv, wth + 2 * HIDN * HIDN, wtl + 2 * HIDN * HIDN,
                                       Wo, woth, wotl);

    // gemm1: fused epilogue writes qkv fp32 + bf16 hi/lo splits
    gemm_bf16x3<<<dim3(3 * HIDN / BN, SEQ / BM), 256, SMEM_DYN>>>(
        xh, xl, wth, wtl, qkv, qkvh, qkvl, 3 * HIDN);

    kg_kernel<<<(NB * HIDN + 255) / 256, 256>>>();
    gate_kernel<<<(NH * SEQ) / 4, 128>>>();
    attn_mma<<<dim3(NB, NH), 128, ATT_SMEM>>>();

    // gemm2: plain fp32 output (final result)
    gemm_bf16x3<<<dim3(HIDN / BN, SEQ / BM), 256, SMEM_DYN>>>(
        atth, attl, woth, wotl, out, nullptr, nullptr, HIDN);
}